// round 3
// baseline (speedup 1.0000x reference)
#include <cuda_runtime.h>
#include <cuda_bf16.h>

// ConvTreeBlock: N=1e6 nodes, C=16, KS=9.
// R3: R1-proven conv shape + (a) 2 threads/node with shfl half-exchange
//     (halves gather wavefronts AND per-thread FMA), (b) stats fused into conv
//     epilogue, (c) BN1+leaky fused into conv2 loads.
// Launches: zero_stats -> conv1(+stats1) -> conv2(BN1 inline, +stats2) -> bnact2.

#define NMAX 1000000

__device__ float g_y1[(size_t)NMAX * 16];   // raw conv1 output
__device__ float g_stats[64];               // [0:16]sum1 [16:32]ssq1 [32:48]sum2 [48:64]ssq2

static constexpr float EPS   = 1e-5f;
static constexpr float SLOPE = 0.2f;

__global__ void k_zero_stats()
{
    if (threadIdx.x < 64) g_stats[threadIdx.x] = 0.0f;
}

// Block = 256 threads = 128 nodes. Thread pair (2*nl, 2*nl+1) owns node nl:
// thread p loads row floats [8p, 8p+8) (2x LDG.128 -> pair shares 128B lines),
// exchanges the half via 8x shfl.xor(1), computes output channels [8p, 8p+8).
// LAYER==2 applies BN1 affine+leaky to loaded values (a,b from g_stats).
// Epilogue: coalesced STG.128 x2 + per-channel sum/ssq via shfl-reduce ->
// smem -> 32 global atomics per block.
template<int LAYER>
__global__ __launch_bounds__(256)
void k_conv(const float* __restrict__ src,     // data (L1) | g_y1 (L2)
            const int*   __restrict__ ind,
            const float* __restrict__ w,       // [c][o][j] : c*144 + o*9 + j
            const float* __restrict__ bias,    // L1 only
            const float* __restrict__ gamma,   // L2: gamma1
            const float* __restrict__ beta,    // L2: beta1
            float*       __restrict__ dst,     // g_y1 (L1) | d_out (L2)
            int n, int stat_off_in, int stat_off_out)
{
    __shared__ __align__(16) float ws[2304];   // ws[j*256 + c*16 + o]
    __shared__ float s_ab[32];                 // a[16], b[16] (LAYER 2)
    __shared__ float s_stat[32];               // sum[16], ssq[16]

    const int tid = threadIdx.x;

    for (int s = tid; s < 2304; s += 256) {
        int o = s & 15, c = (s >> 4) & 15, j = s >> 8;
        ws[s] = w[c * 144 + o * 9 + j];
    }
    if (tid < 32) s_stat[tid] = 0.0f;
    if (LAYER == 2 && tid < 16) {
        float inv  = 1.0f / (float)n;
        float mean = g_stats[stat_off_in + tid] * inv;
        float var  = g_stats[stat_off_in + 16 + tid] * inv - mean * mean;
        float a    = gamma[tid] * rsqrtf(var + EPS);
        s_ab[tid]      = a;
        s_ab[16 + tid] = beta[tid] - a * mean;
    }
    __syncthreads();

    const int nl   = tid >> 1;                 // local node 0..127
    const int p    = tid & 1;                  // half: channels [8p, 8p+8)
    const int node = blockIdx.x * 128 + nl;
    const bool act = node < n;
    const int ibase = act ? node * 9 : 0;      // inactive lanes read ind[0..8] (valid)

    int nj[9];
#pragma unroll
    for (int j = 0; j < 9; ++j) nj[j] = ind[ibase + j];

    float acc[8];
#pragma unroll
    for (int k = 0; k < 8; ++k) acc[k] = (LAYER == 1) ? __ldg(bias + p * 8 + k) : 0.0f;

    // software pipeline: prefetch row-half for j+1 while computing j
    float4 cA, cB, nA, nB;
    {
        const float* rp = src + (size_t)nj[0] * 16 + p * 8;
        cA = *reinterpret_cast<const float4*>(rp);
        cB = *reinterpret_cast<const float4*>(rp + 4);
    }

#pragma unroll 1   // keep body compact (I$ L0); cross-warp MLP hides L2 latency
    for (int j = 0; j < 9; ++j) {
        if (j < 8) {
            const float* rp = src + (size_t)nj[j + 1] * 16 + p * 8;
            nA = *reinterpret_cast<const float4*>(rp);
            nB = *reinterpret_cast<const float4*>(rp + 4);
        }

        float own[8] = {cA.x, cA.y, cA.z, cA.w, cB.x, cB.y, cB.z, cB.w};
        if (LAYER == 2) {
#pragma unroll
            for (int k = 0; k < 8; ++k) {
                float v = fmaf(own[k], s_ab[p * 8 + k], s_ab[16 + p * 8 + k]);
                own[k] = fmaxf(v, SLOPE * v);
            }
        }
        float oth[8];
#pragma unroll
        for (int k = 0; k < 8; ++k) oth[k] = __shfl_xor_sync(0xFFFFFFFFu, own[k], 1);

        float xv[16];
#pragma unroll
        for (int k = 0; k < 8; ++k) {
            xv[p * 8 + k]       = own[k];
            xv[(1 - p) * 8 + k] = oth[k];
        }

        const float* wj = ws + j * 256 + p * 8;
#pragma unroll
        for (int c = 0; c < 16; ++c) {
            float x = xv[c];
            const float4* wv = reinterpret_cast<const float4*>(wj + c * 16);
            float4 w0 = wv[0], w1 = wv[1];
            acc[0] = fmaf(x, w0.x, acc[0]);
            acc[1] = fmaf(x, w0.y, acc[1]);
            acc[2] = fmaf(x, w0.z, acc[2]);
            acc[3] = fmaf(x, w0.w, acc[3]);
            acc[4] = fmaf(x, w1.x, acc[4]);
            acc[5] = fmaf(x, w1.y, acc[5]);
            acc[6] = fmaf(x, w1.z, acc[6]);
            acc[7] = fmaf(x, w1.w, acc[7]);
        }
        cA = nA; cB = nB;
    }

    // ---- store (coalesced STG.128 x2 per thread) ----
    if (act) {
        float4* o4 = reinterpret_cast<float4*>(dst + (size_t)node * 16 + p * 8);
        o4[0] = make_float4(acc[0], acc[1], acc[2], acc[3]);
        o4[1] = make_float4(acc[4], acc[5], acc[6], acc[7]);
    }

    // ---- fused stats: reduce over nodes (xor 2..16 keeps p in bit0) ----
    float m = act ? 1.0f : 0.0f;
    float sv[8], qv[8];
#pragma unroll
    for (int k = 0; k < 8; ++k) { sv[k] = acc[k] * m; qv[k] = acc[k] * acc[k] * m; }
#pragma unroll
    for (int d = 2; d < 32; d <<= 1) {
#pragma unroll
        for (int k = 0; k < 8; ++k) {
            sv[k] += __shfl_xor_sync(0xFFFFFFFFu, sv[k], d);
            qv[k] += __shfl_xor_sync(0xFFFFFFFFu, qv[k], d);
        }
    }
    if ((tid & 31) < 2) {    // lane0: p=0 (ch0..7), lane1: p=1 (ch8..15)
#pragma unroll
        for (int k = 0; k < 8; ++k) {
            atomicAdd(&s_stat[p * 8 + k],      sv[k]);
            atomicAdd(&s_stat[16 + p * 8 + k], qv[k]);
        }
    }
    __syncthreads();
    if (tid < 32) atomicAdd(&g_stats[stat_off_out + tid], s_stat[tid]);
}

// Final: out = leaky(a2[c]*y2 + b2[c] + data), in place on d_out.
__global__ __launch_bounds__(256)
void k_bnact2(const float* __restrict__ gamma,
              const float* __restrict__ beta,
              const float* __restrict__ res,
              float*       __restrict__ out,
              int n, int off)
{
    __shared__ float sa[16], sb[16];
    if (threadIdx.x < 16) {
        int c = threadIdx.x;
        float inv  = 1.0f / (float)n;
        float mean = g_stats[off + c] * inv;
        float var  = g_stats[off + 16 + c] * inv - mean * mean;
        float a    = gamma[c] * rsqrtf(var + EPS);
        sa[c] = a;
        sb[c] = beta[c] - a * mean;
    }
    __syncthreads();

    int n4 = n * 4;
    int stride = gridDim.x * 256;
    for (int i = blockIdx.x * 256 + threadIdx.x; i < n4; i += stride) {
        float4 v = reinterpret_cast<float4*>(out)[i];
        float4 r = reinterpret_cast<const float4*>(res)[i];
        int c0 = (i & 3) * 4;
        v.x = fmaf(v.x, sa[c0 + 0], sb[c0 + 0]) + r.x;  v.x = fmaxf(v.x, SLOPE * v.x);
        v.y = fmaf(v.y, sa[c0 + 1], sb[c0 + 1]) + r.y;  v.y = fmaxf(v.y, SLOPE * v.y);
        v.z = fmaf(v.z, sa[c0 + 2], sb[c0 + 2]) + r.z;  v.z = fmaxf(v.z, SLOPE * v.z);
        v.w = fmaf(v.w, sa[c0 + 3], sb[c0 + 3]) + r.w;  v.w = fmaxf(v.w, SLOPE * v.w);
        reinterpret_cast<float4*>(out)[i] = v;
    }
}

extern "C" void kernel_launch(void* const* d_in, const int* in_sizes, int n_in,
                              void* d_out, int out_size)
{
    const float* data   = (const float*)d_in[0];
    const int*   ind    = (const int*)  d_in[1];
    const float* w1     = (const float*)d_in[2];
    const float* b1     = (const float*)d_in[3];
    const float* gamma1 = (const float*)d_in[4];
    const float* beta1  = (const float*)d_in[5];
    const float* w2     = (const float*)d_in[6];
    const float* gamma2 = (const float*)d_in[7];
    const float* beta2  = (const float*)d_in[8];
    float*       out    = (float*)d_out;

    int n = in_sizes[0] / 16;
    if (n > NMAX) n = NMAX;

    int conv_blocks = (n + 127) / 128;
    int ew_blocks   = 1184;

    k_zero_stats<<<1, 64>>>();
    k_conv<1><<<conv_blocks, 256>>>(data, ind, w1, b1, nullptr, nullptr, g_y1, n, 0, 0);
    k_conv<2><<<conv_blocks, 256>>>(g_y1, ind, w2, nullptr, gamma1, beta1, out, n, 0, 32);
    k_bnact2<<<ew_blocks, 256>>>(gamma2, beta2, data, out, n, 32);
}

// round 4
// speedup vs baseline: 1.0068x; 1.0068x over previous
#include <cuda_runtime.h>
#include <cuda_bf16.h>

// ConvTreeBlock: N=1e6 nodes, C=16, KS=9.
// R4 = R3 with the local-memory spill removed:
//   - no xv[16] (dynamic p-indexed local array) -> two static FMA passes with
//     the p-offset folded into the SHARED-mem weight pointer
//   - no nj[9] local array (ind loaded inside the rolled j-loop)
// Launches: zero_stats -> conv1(+stats1) -> conv2(BN1+leaky inline, +stats2) -> bnact2.

#define NMAX 1000000

__device__ float g_y1[(size_t)NMAX * 16];   // raw conv1 output
__device__ float g_stats[64];               // [0:16]sum1 [16:32]ssq1 [32:48]sum2 [48:64]ssq2

static constexpr float EPS   = 1e-5f;
static constexpr float SLOPE = 0.2f;

__global__ void k_zero_stats()
{
    if (threadIdx.x < 64) g_stats[threadIdx.x] = 0.0f;
}

// Block = 256 threads = 128 nodes. Thread pair (2*nl, 2*nl+1) owns node nl:
// thread p loads row floats [8p, 8p+8) (2x LDG.128, pair shares 128B lines),
// exchanges its half via shfl.xor(1), computes output channels [8p, 8p+8).
// LAYER==2 applies BN1 affine+leaky to loaded values before use/exchange.
template<int LAYER>
__global__ __launch_bounds__(256)
void k_conv(const float* __restrict__ src,     // data (L1) | g_y1 (L2)
            const int*   __restrict__ ind,
            const float* __restrict__ w,       // [c][o][j] : c*144 + o*9 + j
            const float* __restrict__ bias,    // L1 only
            const float* __restrict__ gamma,   // L2: gamma1
            const float* __restrict__ beta,    // L2: beta1
            float*       __restrict__ dst,     // g_y1 (L1) | d_out (L2)
            int n, int stat_off_in, int stat_off_out)
{
    __shared__ __align__(16) float ws[2304];   // ws[j*256 + c*16 + o]
    __shared__ float s_ab[32];                 // a[16], b[16] (LAYER 2)
    __shared__ float s_stat[32];               // sum[16], ssq[16]

    const int tid = threadIdx.x;

    for (int s = tid; s < 2304; s += 256) {
        int o = s & 15, c = (s >> 4) & 15, j = s >> 8;
        ws[s] = w[c * 144 + o * 9 + j];
    }
    if (tid < 32) s_stat[tid] = 0.0f;
    if (LAYER == 2 && tid < 16) {
        float inv  = 1.0f / (float)n;
        float mean = g_stats[stat_off_in + tid] * inv;
        float var  = g_stats[stat_off_in + 16 + tid] * inv - mean * mean;
        float a    = gamma[tid] * rsqrtf(var + EPS);
        s_ab[tid]      = a;
        s_ab[16 + tid] = beta[tid] - a * mean;
    }
    __syncthreads();

    const int nl   = tid >> 1;                 // local node 0..127
    const int p    = tid & 1;                  // half: channels [8p, 8p+8)
    const int node = blockIdx.x * 128 + nl;
    const bool act = node < n;
    const int ibase = act ? node * 9 : 0;      // inactive lanes read valid ind[0..8]

    float acc[8];
#pragma unroll
    for (int k = 0; k < 8; ++k) acc[k] = (LAYER == 1) ? __ldg(bias + p * 8 + k) : 0.0f;

    // per-thread weight views (runtime p offset into SHARED mem: legal, broadcast)
    const float* w_own = ws + (p * 8) * 16 + p * 8;        // own half channels
    const float* w_oth = ws + ((1 - p) * 8) * 16 + p * 8;  // partner half channels

    // software pipeline: prefetch row-half j+1 while computing j
    float4 cA, cB;
    {
        int r0 = ind[ibase];
        const float* rp = src + (size_t)r0 * 16 + p * 8;
        cA = *reinterpret_cast<const float4*>(rp);
        cB = *reinterpret_cast<const float4*>(rp + 4);
    }

#pragma unroll 1   // ~3KB body, fits I$ L0; cross-warp MLP hides L2 latency
    for (int j = 0; j < 9; ++j) {
        float4 nA = make_float4(0.f, 0.f, 0.f, 0.f);
        float4 nB = nA;
        if (j < 8) {
            int rn = ind[ibase + j + 1];
            const float* rp = src + (size_t)rn * 16 + p * 8;
            nA = *reinterpret_cast<const float4*>(rp);
            nB = *reinterpret_cast<const float4*>(rp + 4);
        }

        float own[8] = {cA.x, cA.y, cA.z, cA.w, cB.x, cB.y, cB.z, cB.w};
        if (LAYER == 2) {
#pragma unroll
            for (int k = 0; k < 8; ++k) {
                float v = fmaf(own[k], s_ab[p * 8 + k], s_ab[16 + p * 8 + k]);
                own[k] = fmaxf(v, SLOPE * v);
            }
        }
        float oth[8];
#pragma unroll
        for (int k = 0; k < 8; ++k) oth[k] = __shfl_xor_sync(0xFFFFFFFFu, own[k], 1);

        const float* wj_own = w_own + j * 256;
        const float* wj_oth = w_oth + j * 256;
#pragma unroll
        for (int k = 0; k < 8; ++k) {          // input channel p*8+k
            float x = own[k];
            const float4* wv = reinterpret_cast<const float4*>(wj_own + k * 16);
            float4 w0 = wv[0], w1 = wv[1];
            acc[0] = fmaf(x, w0.x, acc[0]);
            acc[1] = fmaf(x, w0.y, acc[1]);
            acc[2] = fmaf(x, w0.z, acc[2]);
            acc[3] = fmaf(x, w0.w, acc[3]);
            acc[4] = fmaf(x, w1.x, acc[4]);
            acc[5] = fmaf(x, w1.y, acc[5]);
            acc[6] = fmaf(x, w1.z, acc[6]);
            acc[7] = fmaf(x, w1.w, acc[7]);
        }
#pragma unroll
        for (int k = 0; k < 8; ++k) {          // input channel (1-p)*8+k
            float x = oth[k];
            const float4* wv = reinterpret_cast<const float4*>(wj_oth + k * 16);
            float4 w0 = wv[0], w1 = wv[1];
            acc[0] = fmaf(x, w0.x, acc[0]);
            acc[1] = fmaf(x, w0.y, acc[1]);
            acc[2] = fmaf(x, w0.z, acc[2]);
            acc[3] = fmaf(x, w0.w, acc[3]);
            acc[4] = fmaf(x, w1.x, acc[4]);
            acc[5] = fmaf(x, w1.y, acc[5]);
            acc[6] = fmaf(x, w1.z, acc[6]);
            acc[7] = fmaf(x, w1.w, acc[7]);
        }
        cA = nA; cB = nB;
    }

    // ---- store (coalesced STG.128 x2 per thread) ----
    if (act) {
        float4* o4 = reinterpret_cast<float4*>(dst + (size_t)node * 16 + p * 8);
        o4[0] = make_float4(acc[0], acc[1], acc[2], acc[3]);
        o4[1] = make_float4(acc[4], acc[5], acc[6], acc[7]);
    }

    // ---- fused stats: reduce over node lanes (xor 2..16 keeps p in bit0) ----
    float m = act ? 1.0f : 0.0f;
    float sv[8], qv[8];
#pragma unroll
    for (int k = 0; k < 8; ++k) { sv[k] = acc[k] * m; qv[k] = acc[k] * acc[k] * m; }
#pragma unroll
    for (int d = 2; d < 32; d <<= 1) {
#pragma unroll
        for (int k = 0; k < 8; ++k) {
            sv[k] += __shfl_xor_sync(0xFFFFFFFFu, sv[k], d);
            qv[k] += __shfl_xor_sync(0xFFFFFFFFu, qv[k], d);
        }
    }
    if ((tid & 31) < 2) {    // lane0: p=0 (ch0..7), lane1: p=1 (ch8..15)
#pragma unroll
        for (int k = 0; k < 8; ++k) {
            atomicAdd(&s_stat[p * 8 + k],      sv[k]);
            atomicAdd(&s_stat[16 + p * 8 + k], qv[k]);
        }
    }
    __syncthreads();
    if (tid < 32) atomicAdd(&g_stats[stat_off_out + tid], s_stat[tid]);
}

// Final: out = leaky(a2[c]*y2 + b2[c] + data), in place on d_out.
__global__ __launch_bounds__(256)
void k_bnact2(const float* __restrict__ gamma,
              const float* __restrict__ beta,
              const float* __restrict__ res,
              float*       __restrict__ out,
              int n, int off)
{
    __shared__ float sa[16], sb[16];
    if (threadIdx.x < 16) {
        int c = threadIdx.x;
        float inv  = 1.0f / (float)n;
        float mean = g_stats[off + c] * inv;
        float var  = g_stats[off + 16 + c] * inv - mean * mean;
        float a    = gamma[c] * rsqrtf(var + EPS);
        sa[c] = a;
        sb[c] = beta[c] - a * mean;
    }
    __syncthreads();

    int n4 = n * 4;
    int stride = gridDim.x * 256;
    for (int i = blockIdx.x * 256 + threadIdx.x; i < n4; i += stride) {
        float4 v = reinterpret_cast<float4*>(out)[i];
        float4 r = reinterpret_cast<const float4*>(res)[i];
        int c0 = (i & 3) * 4;
        v.x = fmaf(v.x, sa[c0 + 0], sb[c0 + 0]) + r.x;  v.x = fmaxf(v.x, SLOPE * v.x);
        v.y = fmaf(v.y, sa[c0 + 1], sb[c0 + 1]) + r.y;  v.y = fmaxf(v.y, SLOPE * v.y);
        v.z = fmaf(v.z, sa[c0 + 2], sb[c0 + 2]) + r.z;  v.z = fmaxf(v.z, SLOPE * v.z);
        v.w = fmaf(v.w, sa[c0 + 3], sb[c0 + 3]) + r.w;  v.w = fmaxf(v.w, SLOPE * v.w);
        reinterpret_cast<float4*>(out)[i] = v;
    }
}

extern "C" void kernel_launch(void* const* d_in, const int* in_sizes, int n_in,
                              void* d_out, int out_size)
{
    const float* data   = (const float*)d_in[0];
    const int*   ind    = (const int*)  d_in[1];
    const float* w1     = (const float*)d_in[2];
    const float* b1     = (const float*)d_in[3];
    const float* gamma1 = (const float*)d_in[4];
    const float* beta1  = (const float*)d_in[5];
    const float* w2     = (const float*)d_in[6];
    const float* gamma2 = (const float*)d_in[7];
    const float* beta2  = (const float*)d_in[8];
    float*       out    = (float*)d_out;

    int n = in_sizes[0] / 16;
    if (n > NMAX) n = NMAX;

    int conv_blocks = (n + 127) / 128;
    int ew_blocks   = 1184;

    k_zero_stats<<<1, 64>>>();
    k_conv<1><<<conv_blocks, 256>>>(data, ind, w1, b1, nullptr, nullptr, g_y1, n, 0, 0);
    k_conv<2><<<conv_blocks, 256>>>(g_y1, ind, w2, nullptr, gamma1, beta1, out, n, 0, 32);
    k_bnact2<<<ew_blocks, 256>>>(gamma2, beta2, data, out, n, 32);
}

// round 6
// speedup vs baseline: 9.8903x; 9.8238x over previous
#include <cuda_runtime.h>
#include <cuda_bf16.h>

// ConvTreeBlock: N=1e6 nodes, C=16, KS=9.
// R5 = R4 with ONE fix: scratch (g_y1) is selected INSIDE device code, never
// passed as a host-side kernel argument. (Passing a __device__ global from
// host code hands the kernel the HOST shadow address; GB300's ATS/C2C makes
// that silently "work" at ~200GB/s over NVLink-C2C — the entire R2-R4
// regression.)
// Launches: zero_stats -> conv1(+stats1) -> conv2(BN1+leaky inline, +stats2) -> bnact2.

#define NMAX 1000000

__device__ float g_y1[(size_t)NMAX * 16];   // conv1 raw output (device-side only!)
__device__ float g_stats[64];               // [0:16]sum1 [16:32]ssq1 [32:48]sum2 [48:64]ssq2

static constexpr float EPS   = 1e-5f;
static constexpr float SLOPE = 0.2f;

__global__ void k_zero_stats()
{
    if (threadIdx.x < 64) g_stats[threadIdx.x] = 0.0f;
}

// Block = 256 threads = 128 nodes. Thread pair (2*nl, 2*nl+1) owns node nl:
// thread p loads row floats [8p, 8p+8) (2x LDG.128, pair shares 128B lines ->
// 16 wavefronts/LDG instead of 32), exchanges its half via shfl.xor(1),
// computes output channels [8p, 8p+8).
// LAYER==2 applies BN1 affine+leaky to loaded values before use/exchange.
template<int LAYER>
__global__ __launch_bounds__(256)
void k_conv(const float* __restrict__ src_param,  // LAYER1: data
            const int*   __restrict__ ind,
            const float* __restrict__ w,          // [c][o][j] : c*144 + o*9 + j
            const float* __restrict__ bias,       // LAYER1 only
            const float* __restrict__ gamma,      // LAYER2: gamma1
            const float* __restrict__ beta,       // LAYER2: beta1
            float*       __restrict__ dst_param,  // LAYER2: d_out
            int n, int stat_off_in, int stat_off_out)
{
    // device-side scratch selection (the fix)
    const float* src = (LAYER == 1) ? src_param : (const float*)g_y1;
    float*       dst = (LAYER == 1) ? (float*)g_y1 : dst_param;

    __shared__ __align__(16) float ws[2304];   // ws[j*256 + c*16 + o]
    __shared__ float s_ab[32];                 // a[16], b[16] (LAYER 2)
    __shared__ float s_stat[32];               // sum[16], ssq[16]

    const int tid = threadIdx.x;

    for (int s = tid; s < 2304; s += 256) {
        int o = s & 15, c = (s >> 4) & 15, j = s >> 8;
        ws[s] = w[c * 144 + o * 9 + j];
    }
    if (tid < 32) s_stat[tid] = 0.0f;
    if (LAYER == 2 && tid < 16) {
        float inv  = 1.0f / (float)n;
        float mean = g_stats[stat_off_in + tid] * inv;
        float var  = g_stats[stat_off_in + 16 + tid] * inv - mean * mean;
        float a    = gamma[tid] * rsqrtf(var + EPS);
        s_ab[tid]      = a;
        s_ab[16 + tid] = beta[tid] - a * mean;
    }
    __syncthreads();

    const int nl   = tid >> 1;                 // local node 0..127
    const int p    = tid & 1;                  // half: channels [8p, 8p+8)
    const int node = blockIdx.x * 128 + nl;
    const bool act = node < n;
    const int ibase = act ? node * 9 : 0;      // inactive lanes read valid ind[0..8]

    float acc[8];
#pragma unroll
    for (int k = 0; k < 8; ++k) acc[k] = (LAYER == 1) ? __ldg(bias + p * 8 + k) : 0.0f;

    // per-thread weight views (runtime p offset into SHARED mem: 16B-aligned, 2 bcast addrs/warp)
    const float* w_own = ws + (p * 8) * 16 + p * 8;        // own-half input channels
    const float* w_oth = ws + ((1 - p) * 8) * 16 + p * 8;  // partner-half input channels

    // software pipeline: prefetch row-half j+1 while computing j
    float4 cA, cB;
    {
        int r0 = ind[ibase];
        const float* rp = src + (size_t)r0 * 16 + p * 8;
        cA = *reinterpret_cast<const float4*>(rp);
        cB = *reinterpret_cast<const float4*>(rp + 4);
    }

#pragma unroll 1   // ~3KB body, fits I$ L0; cross-warp MLP hides L2 latency
    for (int j = 0; j < 9; ++j) {
        float4 nA = make_float4(0.f, 0.f, 0.f, 0.f);
        float4 nB = nA;
        if (j < 8) {
            int rn = ind[ibase + j + 1];
            const float* rp = src + (size_t)rn * 16 + p * 8;
            nA = *reinterpret_cast<const float4*>(rp);
            nB = *reinterpret_cast<const float4*>(rp + 4);
        }

        float own[8] = {cA.x, cA.y, cA.z, cA.w, cB.x, cB.y, cB.z, cB.w};
        if (LAYER == 2) {
#pragma unroll
            for (int k = 0; k < 8; ++k) {
                float v = fmaf(own[k], s_ab[p * 8 + k], s_ab[16 + p * 8 + k]);
                own[k] = fmaxf(v, SLOPE * v);
            }
        }
        float oth[8];
#pragma unroll
        for (int k = 0; k < 8; ++k) oth[k] = __shfl_xor_sync(0xFFFFFFFFu, own[k], 1);

        const float* wj_own = w_own + j * 256;
        const float* wj_oth = w_oth + j * 256;
#pragma unroll
        for (int k = 0; k < 8; ++k) {          // input channel p*8+k
            float x = own[k];
            const float4* wv = reinterpret_cast<const float4*>(wj_own + k * 16);
            float4 w0 = wv[0], w1 = wv[1];
            acc[0] = fmaf(x, w0.x, acc[0]);
            acc[1] = fmaf(x, w0.y, acc[1]);
            acc[2] = fmaf(x, w0.z, acc[2]);
            acc[3] = fmaf(x, w0.w, acc[3]);
            acc[4] = fmaf(x, w1.x, acc[4]);
            acc[5] = fmaf(x, w1.y, acc[5]);
            acc[6] = fmaf(x, w1.z, acc[6]);
            acc[7] = fmaf(x, w1.w, acc[7]);
        }
#pragma unroll
        for (int k = 0; k < 8; ++k) {          // input channel (1-p)*8+k
            float x = oth[k];
            const float4* wv = reinterpret_cast<const float4*>(wj_oth + k * 16);
            float4 w0 = wv[0], w1 = wv[1];
            acc[0] = fmaf(x, w0.x, acc[0]);
            acc[1] = fmaf(x, w0.y, acc[1]);
            acc[2] = fmaf(x, w0.z, acc[2]);
            acc[3] = fmaf(x, w0.w, acc[3]);
            acc[4] = fmaf(x, w1.x, acc[4]);
            acc[5] = fmaf(x, w1.y, acc[5]);
            acc[6] = fmaf(x, w1.z, acc[6]);
            acc[7] = fmaf(x, w1.w, acc[7]);
        }
        cA = nA; cB = nB;
    }

    // ---- store (coalesced STG.128 x2 per thread) ----
    if (act) {
        float4* o4 = reinterpret_cast<float4*>(dst + (size_t)node * 16 + p * 8);
        o4[0] = make_float4(acc[0], acc[1], acc[2], acc[3]);
        o4[1] = make_float4(acc[4], acc[5], acc[6], acc[7]);
    }

    // ---- fused stats: reduce over node lanes (xor 2..16 keeps p in bit0) ----
    float m = act ? 1.0f : 0.0f;
    float sv[8], qv[8];
#pragma unroll
    for (int k = 0; k < 8; ++k) { sv[k] = acc[k] * m; qv[k] = acc[k] * acc[k] * m; }
#pragma unroll
    for (int d = 2; d < 32; d <<= 1) {
#pragma unroll
        for (int k = 0; k < 8; ++k) {
            sv[k] += __shfl_xor_sync(0xFFFFFFFFu, sv[k], d);
            qv[k] += __shfl_xor_sync(0xFFFFFFFFu, qv[k], d);
        }
    }
    if ((tid & 31) < 2) {    // lane0: p=0 (ch0..7), lane1: p=1 (ch8..15)
#pragma unroll
        for (int k = 0; k < 8; ++k) {
            atomicAdd(&s_stat[p * 8 + k],      sv[k]);
            atomicAdd(&s_stat[16 + p * 8 + k], qv[k]);
        }
    }
    __syncthreads();
    if (tid < 32) atomicAdd(&g_stats[stat_off_out + tid], s_stat[tid]);
}

// Final: out = leaky(a2[c]*y2 + b2[c] + data), in place on d_out.
__global__ __launch_bounds__(256)
void k_bnact2(const float* __restrict__ gamma,
              const float* __restrict__ beta,
              const float* __restrict__ res,
              float*       __restrict__ out,
              int n, int off)
{
    __shared__ float sa[16], sb[16];
    if (threadIdx.x < 16) {
        int c = threadIdx.x;
        float inv  = 1.0f / (float)n;
        float mean = g_stats[off + c] * inv;
        float var  = g_stats[off + 16 + c] * inv - mean * mean;
        float a    = gamma[c] * rsqrtf(var + EPS);
        sa[c] = a;
        sb[c] = beta[c] - a * mean;
    }
    __syncthreads();

    int n4 = n * 4;
    int stride = gridDim.x * 256;
    for (int i = blockIdx.x * 256 + threadIdx.x; i < n4; i += stride) {
        float4 v = reinterpret_cast<float4*>(out)[i];
        float4 r = reinterpret_cast<const float4*>(res)[i];
        int c0 = (i & 3) * 4;
        v.x = fmaf(v.x, sa[c0 + 0], sb[c0 + 0]) + r.x;  v.x = fmaxf(v.x, SLOPE * v.x);
        v.y = fmaf(v.y, sa[c0 + 1], sb[c0 + 1]) + r.y;  v.y = fmaxf(v.y, SLOPE * v.y);
        v.z = fmaf(v.z, sa[c0 + 2], sb[c0 + 2]) + r.z;  v.z = fmaxf(v.z, SLOPE * v.z);
        v.w = fmaf(v.w, sa[c0 + 3], sb[c0 + 3]) + r.w;  v.w = fmaxf(v.w, SLOPE * v.w);
        reinterpret_cast<float4*>(out)[i] = v;
    }
}

extern "C" void kernel_launch(void* const* d_in, const int* in_sizes, int n_in,
                              void* d_out, int out_size)
{
    const float* data   = (const float*)d_in[0];
    const int*   ind    = (const int*)  d_in[1];
    const float* w1     = (const float*)d_in[2];
    const float* b1     = (const float*)d_in[3];
    const float* gamma1 = (const float*)d_in[4];
    const float* beta1  = (const float*)d_in[5];
    const float* w2     = (const float*)d_in[6];
    const float* gamma2 = (const float*)d_in[7];
    const float* beta2  = (const float*)d_in[8];
    float*       out    = (float*)d_out;

    int n = in_sizes[0] / 16;
    if (n > NMAX) n = NMAX;

    int conv_blocks = (n + 127) / 128;
    int ew_blocks   = 1184;

    k_zero_stats<<<1, 64>>>();
    // NOTE: no __device__ symbol is ever passed as an argument.
    k_conv<1><<<conv_blocks, 256>>>(data, ind, w1, b1, nullptr, nullptr, nullptr, n, 0, 0);
    k_conv<2><<<conv_blocks, 256>>>(nullptr, ind, w2, nullptr, gamma1, beta1, out, n, 0, 32);
    k_bnact2<<<ew_blocks, 256>>>(gamma2, beta2, data, out, n, 32);
}